// round 16
// baseline (speedup 1.0000x reference)
#include <cuda_runtime.h>
#include <cstdint>

// EdgeBlock fused MLP, TF32 mma.sync. Round 16 = R15 + pair-permuted smem:
//  within each 8-col block, col j stored at (j<4 ? 2j : 2(j-4)+1) so fragment
//  pairs (k+c, k+c+4) are adjacent -> LDS.64 A-fragment loads (half the LDS
//  instructions, same wavefront bytes). Strides 136/72 (== 8 mod 32) keep
//  LDS.64 bankpair-conflict-free (4g+c per phase); staging STS still
//  conflict-free (lane-bijective permutation).
// x = [edges(32) | nodes[send](32) | nodes[recv](32) | globals[batch](16)]  (K=112)
// h = relu(x @ W1 + b1) (64);  y = h @ W2 + b2 (32)

#define TILE_M 128
#define NTHREADS 256

#define SX_STRIDE 136       // == 8 mod 32; LDS.64 bankpair 4g+c conflict-free
#define SH_STRIDE 72        // == 8 mod 32
#define SMEM_BYTES (TILE_M * SX_STRIDE * 4)   // 69632 -> 3 CTAs/SM (209KB)

// fragment-packed weights: W1P[(ks*8+nt)*32 + lane] = (b0,b1)
__device__ float2 d_W1P[14 * 8 * 32];
__device__ float2 d_W2P[8 * 4 * 32];

__device__ __forceinline__ float tf32_rna(float x) {
    unsigned u;
    asm("cvt.rna.tf32.f32 %0, %1;" : "=r"(u) : "f"(x));
    return __uint_as_float(u);
}

// within-8-block pair permutation: j -> (j<4 ? 2j : 2(j-4)+1); high bits pass.
__device__ __forceinline__ int perm_col(int col) {
    return (col & ~7) | ((col & 3) << 1) | ((col >> 2) & 1);
}

__device__ __forceinline__ void mma_tf32_16x8x8(float* c, const unsigned* a,
                                                unsigned b0, unsigned b1) {
    asm volatile(
        "mma.sync.aligned.m16n8k8.row.col.f32.tf32.tf32.f32 "
        "{%0,%1,%2,%3}, {%4,%5,%6,%7}, {%8,%9}, {%0,%1,%2,%3};"
        : "+f"(c[0]), "+f"(c[1]), "+f"(c[2]), "+f"(c[3])
        : "r"(a[0]), "r"(a[1]), "r"(a[2]), "r"(a[3]), "r"(b0), "r"(b1));
}

__global__ void prep_weights(const float* __restrict__ W1,
                             const float* __restrict__ W2) {
    int i = blockIdx.x * blockDim.x + threadIdx.x;
    if (i < 14 * 8 * 32) {
        int lane = i & 31, nt = (i >> 5) & 7, ks = i >> 8;
        int g = lane >> 2, c = lane & 3;
        float b0 = W1[(ks * 8 + c) * 64 + nt * 8 + g];
        float b1 = W1[(ks * 8 + c + 4) * 64 + nt * 8 + g];
        d_W1P[i] = make_float2(tf32_rna(b0), tf32_rna(b1));
    }
    if (i < 8 * 4 * 32) {
        int lane = i & 31, nt = (i >> 5) & 3, ks = i >> 7;
        int g = lane >> 2, c = lane & 3;
        float b0 = W2[(ks * 8 + c) * 32 + nt * 8 + g];
        float b1 = W2[(ks * 8 + c + 4) * 32 + nt * 8 + g];
        d_W2P[i] = make_float2(tf32_rna(b0), tf32_rna(b1));
    }
}

__global__ void __launch_bounds__(NTHREADS, 3)
edgeblock_kernel(const float* __restrict__ nodes,
                 const float* __restrict__ edges,
                 const float* __restrict__ graph_globals,
                 const int*   __restrict__ send,
                 const int*   __restrict__ recv,
                 const int*   __restrict__ batch_edges,
                 const float* __restrict__ b1,
                 const float* __restrict__ b2,
                 float*       __restrict__ out) {
    extern __shared__ float sm[];
    float* sX = sm;                      // [128][136] tf32, pair-permuted (aliased by sH)

    const int t     = threadIdx.x;
    const int e0    = blockIdx.x * TILE_M;
    const int lane  = t & 31;
    const int w     = t >> 5;            // warp id 0..7

    // ---- stage x tile: one warp = one full row per step; permuted positions ----
    {
        const int sbase = w * 16;        // staging rows [sbase, sbase+16)
        const int pl  = perm_col(lane);          // 0..31 bijective
        const int plg = perm_col(lane & 15);     // 0..15 bijective
        int idxS = __ldg(send        + e0 + sbase + (lane & 15));
        int idxR = __ldg(recv        + e0 + sbase + (lane & 15));
        int idxB = __ldg(batch_edges + e0 + sbase + (lane & 15));
#pragma unroll
        for (int rr = 0; rr < 16; rr++) {
            int e = sbase + rr;
            float* row = sX + e * SX_STRIDE;
            row[pl] = tf32_rna(edges[(size_t)(e0 + e) * 32 + lane]);
            int ns = __shfl_sync(0xffffffffu, idxS, rr);
            row[32 + pl] = tf32_rna(nodes[(size_t)ns * 32 + lane]);
            int nr = __shfl_sync(0xffffffffu, idxR, rr);
            row[64 + pl] = tf32_rna(nodes[(size_t)nr * 32 + lane]);
        }
#pragma unroll
        for (int rr = 0; rr < 8; rr++) {
            int e  = sbase + rr * 2 + (lane >> 4);
            int gb = __shfl_sync(0xffffffffu, idxB, rr * 2 + (lane >> 4));
            sX[e * SX_STRIDE + 96 + plg] =
                tf32_rna(graph_globals[(size_t)gb * 16 + (lane & 15)]);
        }
    }
    __syncthreads();

    // ---- warp grid: wr in 0..3 (row groups of 32), wc in 0..1 (col halves) ----
    const int wr = w & 3;
    const int wc = w >> 2;
    const int g  = lane >> 2;
    const int c  = lane & 3;
    const int R  = wr * 32;              // m-tiles at rows R and R+16

    // ---- layer 1: rows [R,R+32) x cols [wc*32, wc*32+32) ----
    float acc[2][4][4];
#pragma unroll
    for (int mt = 0; mt < 2; mt++)
#pragma unroll
        for (int nl = 0; nl < 4; nl++)
#pragma unroll
            for (int q = 0; q < 4; q++) acc[mt][nl][q] = 0.0f;

    {
        // pair-permuted: cols (k+c, k+c+4) live at float offset k + 2c
        const float2* pA0 = (const float2*)(sX + (R + g) * SX_STRIDE) + c;       // +4/ks
        const float2* pA1 = (const float2*)(sX + (R + g + 8) * SX_STRIDE) + c;
        const float2* pA2 = (const float2*)(sX + (R + g + 16) * SX_STRIDE) + c;
        const float2* pA3 = (const float2*)(sX + (R + g + 24) * SX_STRIDE) + c;
        const float2* pB  = d_W1P + (wc * 4) * 32 + lane;                        // +256/ks

#pragma unroll 2
        for (int ks = 0; ks < 14; ks++) {
            float2 b0 = __ldg(pB);
            float2 b1v = __ldg(pB + 32);
            float2 b2v = __ldg(pB + 64);
            float2 b3 = __ldg(pB + 96);
            float2 q0 = pA0[0];          // {x[k+c], x[k+c+4]} row r
            float2 q1 = pA1[0];          // row r+8
            unsigned a[4];
            a[0] = __float_as_uint(q0.x);
            a[1] = __float_as_uint(q1.x);
            a[2] = __float_as_uint(q0.y);
            a[3] = __float_as_uint(q1.y);
            mma_tf32_16x8x8(acc[0][0], a, __float_as_uint(b0.x),  __float_as_uint(b0.y));
            mma_tf32_16x8x8(acc[0][1], a, __float_as_uint(b1v.x), __float_as_uint(b1v.y));
            mma_tf32_16x8x8(acc[0][2], a, __float_as_uint(b2v.x), __float_as_uint(b2v.y));
            mma_tf32_16x8x8(acc[0][3], a, __float_as_uint(b3.x),  __float_as_uint(b3.y));
            q0 = pA2[0];
            q1 = pA3[0];
            a[0] = __float_as_uint(q0.x);
            a[1] = __float_as_uint(q1.x);
            a[2] = __float_as_uint(q0.y);
            a[3] = __float_as_uint(q1.y);
            mma_tf32_16x8x8(acc[1][0], a, __float_as_uint(b0.x),  __float_as_uint(b0.y));
            mma_tf32_16x8x8(acc[1][1], a, __float_as_uint(b1v.x), __float_as_uint(b1v.y));
            mma_tf32_16x8x8(acc[1][2], a, __float_as_uint(b2v.x), __float_as_uint(b2v.y));
            mma_tf32_16x8x8(acc[1][3], a, __float_as_uint(b3.x),  __float_as_uint(b3.y));
            pA0 += 4; pA1 += 4; pA2 += 4; pA3 += 4;
            pB  += 256;
        }
    }
    __syncthreads();   // all warps done reading sX; sH aliases it

    // ---- bias + relu + tf32 -> smem h (pair-permuted positions) ----
    float* sH = sm;   // [128][72] pair-permuted
    const int p0 = ((2 * c) & 3) << 1;             // position of col 2c   in its 8-block
    const int p1 = (((2 * c + 1) & 3) << 1) | ((c >> 1) & 1) * 0 + (((2 * c + 1) >> 2) & 1);
    // note: p1 = ((2c+1)&3)<<1 | ((2c+1)>>2)&1
#pragma unroll
    for (int mt = 0; mt < 2; mt++) {
        int r = R + mt * 16 + g;
#pragma unroll
        for (int nl = 0; nl < 4; nl++) {
            int base = (wc * 4 + nl) * 8;
            int col  = base + 2 * c;
            float bb0 = __ldg(b1 + col), bb1 = __ldg(b1 + col + 1);
            int q0p = base + ((col & 3) << 1) + ((col >> 2) & 1);
            int q1p = base + (((col + 1) & 3) << 1) + (((col + 1) >> 2) & 1);
            sH[r * SH_STRIDE + q0p]       = tf32_rna(fmaxf(acc[mt][nl][0] + bb0, 0.0f));
            sH[r * SH_STRIDE + q1p]       = tf32_rna(fmaxf(acc[mt][nl][1] + bb1, 0.0f));
            sH[(r + 8) * SH_STRIDE + q0p] = tf32_rna(fmaxf(acc[mt][nl][2] + bb0, 0.0f));
            sH[(r + 8) * SH_STRIDE + q1p] = tf32_rna(fmaxf(acc[mt][nl][3] + bb1, 0.0f));
        }
    }
    __syncthreads();
    (void)p0; (void)p1;

    // ---- layer 2: rows [R,R+32) x cols [wc*16, wc*16+16) ----
    float d2[2][2][4];
#pragma unroll
    for (int mt = 0; mt < 2; mt++)
#pragma unroll
        for (int nl = 0; nl < 2; nl++)
#pragma unroll
            for (int q = 0; q < 4; q++) d2[mt][nl][q] = 0.0f;

    {
        const float2* pH0 = (const float2*)(sH + (R + g) * SH_STRIDE) + c;
        const float2* pH1 = (const float2*)(sH + (R + g + 8) * SH_STRIDE) + c;
        const float2* pH2 = (const float2*)(sH + (R + g + 16) * SH_STRIDE) + c;
        const float2* pH3 = (const float2*)(sH + (R + g + 24) * SH_STRIDE) + c;
        const float2* pB2 = d_W2P + (wc * 2) * 32 + lane;

#pragma unroll
        for (int ks = 0; ks < 8; ks++) {
            float2 b0 = __ldg(pB2 + ks * 128);
            float2 b1v = __ldg(pB2 + ks * 128 + 32);
            float2 q0 = pH0[ks * 4];
            float2 q1 = pH1[ks * 4];
            unsigned a[4];
            a[0] = __float_as_uint(q0.x);
            a[1] = __float_as_uint(q1.x);
            a[2] = __float_as_uint(q0.y);
            a[3] = __float_as_uint(q1.y);
            mma_tf32_16x8x8(d2[0][0], a, __float_as_uint(b0.x),  __float_as_uint(b0.y));
            mma_tf32_16x8x8(d2[0][1], a, __float_as_uint(b1v.x), __float_as_uint(b1v.y));
            q0 = pH2[ks * 4];
            q1 = pH3[ks * 4];
            a[0] = __float_as_uint(q0.x);
            a[1] = __float_as_uint(q1.x);
            a[2] = __float_as_uint(q0.y);
            a[3] = __float_as_uint(q1.y);
            mma_tf32_16x8x8(d2[1][0], a, __float_as_uint(b0.x),  __float_as_uint(b0.y));
            mma_tf32_16x8x8(d2[1][1], a, __float_as_uint(b1v.x), __float_as_uint(b1v.y));
        }
    }

    // ---- epilogue: bias + store out[E,32] ----
#pragma unroll
    for (int mt = 0; mt < 2; mt++) {
        int r = R + mt * 16 + g;
#pragma unroll
        for (int nl = 0; nl < 2; nl++) {
            int col = (wc * 2 + nl) * 8 + 2 * c;
            float bb0 = __ldg(b2 + col), bb1 = __ldg(b2 + col + 1);
            float2 v0 = make_float2(d2[mt][nl][0] + bb0, d2[mt][nl][1] + bb1);
            float2 v1 = make_float2(d2[mt][nl][2] + bb0, d2[mt][nl][3] + bb1);
            *reinterpret_cast<float2*>(out + (size_t)(e0 + r) * 32 + col)     = v0;
            *reinterpret_cast<float2*>(out + (size_t)(e0 + r + 8) * 32 + col) = v1;
        }
    }
}

extern "C" void kernel_launch(void* const* d_in, const int* in_sizes, int n_in,
                              void* d_out, int out_size) {
    const float* nodes         = (const float*)d_in[0];
    const float* edges         = (const float*)d_in[1];
    const float* graph_globals = (const float*)d_in[2];
    const int*   send          = (const int*)d_in[3];
    const int*   recv          = (const int*)d_in[4];
    const int*   batch_edges   = (const int*)d_in[5];
    const float* W1            = (const float*)d_in[6];
    const float* b1            = (const float*)d_in[7];
    const float* W2            = (const float*)d_in[8];
    const float* b2            = (const float*)d_in[9];
    float*       out           = (float*)d_out;

    const int n_edges = in_sizes[1] / 32;          // 1,600,000
    const int grid    = (n_edges + TILE_M - 1) / TILE_M;

    prep_weights<<<(14 * 8 * 32 + 255) / 256, 256>>>(W1, W2);

    cudaFuncSetAttribute(edgeblock_kernel,
                         cudaFuncAttributeMaxDynamicSharedMemorySize, SMEM_BYTES);
    edgeblock_kernel<<<grid, NTHREADS, SMEM_BYTES>>>(
        nodes, edges, graph_globals, send, recv, batch_edges,
        b1, b2, out);
}

// round 17
// speedup vs baseline: 1.1172x; 1.1172x over previous
#include <cuda_runtime.h>
#include <cuda_fp16.h>
#include <cstdint>

// EdgeBlock fused MLP, FP16 mma.sync m16n8k16 (fp32 accumulate). Round 17 =
// R15 structure (4x2 warp grid, smem h, incremental pointers) with the whole
// datapath in half precision: half the K-steps, half the operand bytes, half
// the L1 wavefronts. fp16 mantissa == tf32 mantissa -> accuracy comparable.
// x = [edges(32) | nodes[send](32) | nodes[recv](32) | globals[batch](16)]  (K=112)
// h = relu(x @ W1 + b1) (64);  y = h @ W2 + b2 (32)

#define TILE_M 128
#define NTHREADS 256

#define SX_WSTR 60          // x row stride in 4B words (120 halfs); 60%32=28 -> banks 28g+c distinct
#define SH_WSTR 36          // h row stride in words (72 halfs); 36%32=4 -> banks 4g+c distinct
#define SMEM_BYTES (TILE_M * SX_WSTR * 4)   // 30720 -> 3 CTAs/SM easily

// packed weights: W1P[(ks*8+nt)*32+lane] = uint2{ h2(W[16ks+2c][n],W[+1]), h2(W[+8],W[+9]) }
__device__ uint2 d_W1Ph[7 * 8 * 32];
__device__ uint2 d_W2Ph[4 * 4 * 32];

__device__ __forceinline__ unsigned h2u(__half2 h) {
    return *reinterpret_cast<unsigned*>(&h);
}

__device__ __forceinline__ void mma_f16_16x8x16(float* c, const unsigned* a,
                                                unsigned b0, unsigned b1) {
    asm volatile(
        "mma.sync.aligned.m16n8k16.row.col.f32.f16.f16.f32 "
        "{%0,%1,%2,%3}, {%4,%5,%6,%7}, {%8,%9}, {%0,%1,%2,%3};"
        : "+f"(c[0]), "+f"(c[1]), "+f"(c[2]), "+f"(c[3])
        : "r"(a[0]), "r"(a[1]), "r"(a[2]), "r"(a[3]), "r"(b0), "r"(b1));
}

__global__ void prep_weights(const float* __restrict__ W1,
                             const float* __restrict__ W2) {
    int i = blockIdx.x * blockDim.x + threadIdx.x;
    if (i < 7 * 8 * 32) {
        int lane = i & 31, nt = (i >> 5) & 7, ks = i >> 8;
        int g = lane >> 2, c = lane & 3;
        int n = nt * 8 + g, k0 = ks * 16 + 2 * c;
        __half2 lo = __floats2half2_rn(W1[k0 * 64 + n],       W1[(k0 + 1) * 64 + n]);
        __half2 hi = __floats2half2_rn(W1[(k0 + 8) * 64 + n], W1[(k0 + 9) * 64 + n]);
        d_W1Ph[i] = make_uint2(h2u(lo), h2u(hi));
    }
    if (i < 4 * 4 * 32) {
        int lane = i & 31, nt = (i >> 5) & 3, ks = i >> 7;
        int g = lane >> 2, c = lane & 3;
        int n = nt * 8 + g, k0 = ks * 16 + 2 * c;
        __half2 lo = __floats2half2_rn(W2[k0 * 32 + n],       W2[(k0 + 1) * 32 + n]);
        __half2 hi = __floats2half2_rn(W2[(k0 + 8) * 32 + n], W2[(k0 + 9) * 32 + n]);
        d_W2Ph[i] = make_uint2(h2u(lo), h2u(hi));
    }
}

__global__ void __launch_bounds__(NTHREADS, 3)
edgeblock_kernel(const float* __restrict__ nodes,
                 const float* __restrict__ edges,
                 const float* __restrict__ graph_globals,
                 const int*   __restrict__ send,
                 const int*   __restrict__ recv,
                 const int*   __restrict__ batch_edges,
                 const float* __restrict__ b1,
                 const float* __restrict__ b2,
                 float*       __restrict__ out) {
    extern __shared__ unsigned smw[];    // x tile as half2 words [128][60] (aliased by h [128][36])

    const int t     = threadIdx.x;
    const int e0    = blockIdx.x * TILE_M;
    const int lane  = t & 31;
    const int w     = t >> 5;            // warp id 0..7

    // ---- stage x tile as half2, one full row per warp step (conflict-free STS) ----
    {
        const int sbase = w * 16;        // staging rows [sbase, sbase+16)
        int idxS = __ldg(send        + e0 + sbase + (lane & 15));
        int idxR = __ldg(recv        + e0 + sbase + (lane & 15));
        int idxB = __ldg(batch_edges + e0 + sbase + (lane & 15));
#pragma unroll
        for (int rr = 0; rr < 16; rr++) {
            int e = sbase + rr;
            unsigned* row = smw + e * SX_WSTR;
            int ns = __shfl_sync(0xffffffffu, idxS, rr);
            // pass 1: words 0..31  (edges cols 0..31 | src cols 32..63)
            {
                const float* src = (lane < 16)
                    ? (edges + (size_t)(e0 + e) * 32 + 2 * lane)
                    : (nodes + (size_t)ns * 32 + 2 * (lane - 16));
                float2 v = *reinterpret_cast<const float2*>(src);
                row[lane] = h2u(__floats2half2_rn(v.x, v.y));
            }
            int nr = __shfl_sync(0xffffffffu, idxR, rr);
            int gb = __shfl_sync(0xffffffffu, idxB, rr);
            // pass 2: words 32..55  (dst cols 64..95 | globals cols 96..111)
            if (lane < 24) {
                const float* src = (lane < 16)
                    ? (nodes + (size_t)nr * 32 + 2 * lane)
                    : (graph_globals + (size_t)gb * 16 + 2 * (lane - 16));
                float2 v = *reinterpret_cast<const float2*>(src);
                row[32 + lane] = h2u(__floats2half2_rn(v.x, v.y));
            }
        }
    }
    __syncthreads();

    // ---- warp grid: wr in 0..3 (row groups of 32), wc in 0..1 (col halves) ----
    const int wr = w & 3;
    const int wc = w >> 2;
    const int g  = lane >> 2;
    const int c  = lane & 3;
    const int R  = wr * 32;              // m-tiles at rows R and R+16

    // ---- layer 1: rows [R,R+32) x cols [wc*32, wc*32+32), 7 k16-steps ----
    float acc[2][4][4];
#pragma unroll
    for (int mt = 0; mt < 2; mt++)
#pragma unroll
        for (int nl = 0; nl < 4; nl++)
#pragma unroll
            for (int q = 0; q < 4; q++) acc[mt][nl][q] = 0.0f;

    {
        const unsigned* pA0 = smw + (R + g) * SX_WSTR + c;       // [0]: k2c pair, [4]: k2c+8 pair
        const unsigned* pA1 = pA0 + 8 * SX_WSTR;
        const unsigned* pA2 = pA0 + 16 * SX_WSTR;
        const unsigned* pA3 = pA0 + 24 * SX_WSTR;
        const uint2*    pB  = d_W1Ph + (wc * 4) * 32 + lane;     // +32/nt, +256/ks

#pragma unroll 1
        for (int ks = 0; ks < 7; ks++) {
            uint2 B0 = __ldg(pB);
            uint2 B1 = __ldg(pB + 32);
            uint2 B2 = __ldg(pB + 64);
            uint2 B3 = __ldg(pB + 96);
            unsigned a[4];
            a[0] = pA0[0]; a[1] = pA1[0]; a[2] = pA0[4]; a[3] = pA1[4];
            mma_f16_16x8x16(acc[0][0], a, B0.x, B0.y);
            mma_f16_16x8x16(acc[0][1], a, B1.x, B1.y);
            mma_f16_16x8x16(acc[0][2], a, B2.x, B2.y);
            mma_f16_16x8x16(acc[0][3], a, B3.x, B3.y);
            a[0] = pA2[0]; a[1] = pA3[0]; a[2] = pA2[4]; a[3] = pA3[4];
            mma_f16_16x8x16(acc[1][0], a, B0.x, B0.y);
            mma_f16_16x8x16(acc[1][1], a, B1.x, B1.y);
            mma_f16_16x8x16(acc[1][2], a, B2.x, B2.y);
            mma_f16_16x8x16(acc[1][3], a, B3.x, B3.y);
            pA0 += 8; pA1 += 8; pA2 += 8; pA3 += 8;
            pB  += 256;
        }
    }
    __syncthreads();   // all warps done reading sX; h aliases it

    // ---- bias + relu -> half2 smem h (C-fragment cols (2c,2c+1) pack natively) ----
#pragma unroll
    for (int mt = 0; mt < 2; mt++) {
        int r = R + mt * 16 + g;
#pragma unroll
        for (int nl = 0; nl < 4; nl++) {
            int col = (wc * 4 + nl) * 8 + 2 * c;
            float2 bb = __ldg(reinterpret_cast<const float2*>(b1 + col));
            float h0 = fmaxf(acc[mt][nl][0] + bb.x, 0.0f);
            float h1 = fmaxf(acc[mt][nl][1] + bb.y, 0.0f);
            float h2 = fmaxf(acc[mt][nl][2] + bb.x, 0.0f);
            float h3 = fmaxf(acc[mt][nl][3] + bb.y, 0.0f);
            smw[r * SH_WSTR + (col >> 1)]       = h2u(__floats2half2_rn(h0, h1));
            smw[(r + 8) * SH_WSTR + (col >> 1)] = h2u(__floats2half2_rn(h2, h3));
        }
    }
    __syncthreads();

    // ---- layer 2: rows [R,R+32) x cols [wc*16, wc*16+16), 4 k16-steps ----
    float d2[2][2][4];
#pragma unroll
    for (int mt = 0; mt < 2; mt++)
#pragma unroll
        for (int nl = 0; nl < 2; nl++)
#pragma unroll
            for (int q = 0; q < 4; q++) d2[mt][nl][q] = 0.0f;

    {
        const unsigned* pH0 = smw + (R + g) * SH_WSTR + c;
        const unsigned* pH1 = pH0 + 8 * SH_WSTR;
        const unsigned* pH2 = pH0 + 16 * SH_WSTR;
        const unsigned* pH3 = pH0 + 24 * SH_WSTR;
        const uint2*    pB2 = d_W2Ph + (wc * 2) * 32 + lane;     // +32/nt, +128/ks

#pragma unroll
        for (int ks = 0; ks < 4; ks++) {
            uint2 B0 = __ldg(pB2 + ks * 128);
            uint2 B1 = __ldg(pB2 + ks * 128 + 32);
            unsigned a[4];
            a[0] = pH0[ks * 8]; a[1] = pH1[ks * 8];
            a[2] = pH0[ks * 8 + 4]; a[3] = pH1[ks * 8 + 4];
            mma_f16_16x8x16(d2[0][0], a, B0.x, B0.y);
            mma_f16_16x8x16(d2[0][1], a, B1.x, B1.y);
            a[0] = pH2[ks * 8]; a[1] = pH3[ks * 8];
            a[2] = pH2[ks * 8 + 4]; a[3] = pH3[ks * 8 + 4];
            mma_f16_16x8x16(d2[1][0], a, B0.x, B0.y);
            mma_f16_16x8x16(d2[1][1], a, B1.x, B1.y);
        }
    }

    // ---- epilogue: bias + store out[E,32] (fp32) ----
#pragma unroll
    for (int mt = 0; mt < 2; mt++) {
        int r = R + mt * 16 + g;
#pragma unroll
        for (int nl = 0; nl < 2; nl++) {
            int col = (wc * 2 + nl) * 8 + 2 * c;
            float2 bb = __ldg(reinterpret_cast<const float2*>(b2 + col));
            float2 v0 = make_float2(d2[mt][nl][0] + bb.x, d2[mt][nl][1] + bb.y);
            float2 v1 = make_float2(d2[mt][nl][2] + bb.x, d2[mt][nl][3] + bb.y);
            *reinterpret_cast<float2*>(out + (size_t)(e0 + r) * 32 + col)     = v0;
            *reinterpret_cast<float2*>(out + (size_t)(e0 + r + 8) * 32 + col) = v1;
        }
    }
}

extern "C" void kernel_launch(void* const* d_in, const int* in_sizes, int n_in,
                              void* d_out, int out_size) {
    const float* nodes         = (const float*)d_in[0];
    const float* edges         = (const float*)d_in[1];
    const float* graph_globals = (const float*)d_in[2];
    const int*   send          = (const int*)d_in[3];
    const int*   recv          = (const int*)d_in[4];
    const int*   batch_edges   = (const int*)d_in[5];
    const float* W1            = (const float*)d_in[6];
    const float* b1            = (const float*)d_in[7];
    const float* W2            = (const float*)d_in[8];
    const float* b2            = (const float*)d_in[9];
    float*       out           = (float*)d_out;

    const int n_edges = in_sizes[1] / 32;          // 1,600,000
    const int grid    = (n_edges + TILE_M - 1) / TILE_M;

    prep_weights<<<(7 * 8 * 32 + 255) / 256, 256>>>(W1, W2);

    cudaFuncSetAttribute(edgeblock_kernel,
                         cudaFuncAttributeMaxDynamicSharedMemorySize, SMEM_BYTES);
    edgeblock_kernel<<<grid, NTHREADS, SMEM_BYTES>>>(
        nodes, edges, graph_globals, send, recv, batch_edges,
        b1, b2, out);
}